// round 14
// baseline (speedup 1.0000x reference)
#include <cuda_runtime.h>
#include <cstdint>

#define EMBED   1024
#define HEADS   16
#define HDIM    64
#define BATCH   2
#define SEQ     2048
#define MTOT    (BATCH*SEQ)   // 4096

// Scratch (static __device__ -- no dynamic allocation allowed)
__device__ float g_qkv [(size_t)MTOT * 3 * EMBED];   // [4096, 3072]
__device__ float g_attn[(size_t)MTOT * EMBED];       // [4096, 1024]

// ============================================================================
// helpers
// ============================================================================
__device__ __forceinline__ uint32_t smem_u32(const void* p) {
    uint32_t a;
    asm("{ .reg .u64 t; cvta.to.shared.u64 t, %1; cvt.u32.u64 %0, t; }"
        : "=r"(a) : "l"(p));
    return a;
}
__device__ __forceinline__ float f2tf32(float x) {
    uint32_t u;
    asm("cvt.rna.tf32.f32 %0, %1;" : "=r"(u) : "f"(x));
    return __uint_as_float(u);
}
__device__ __forceinline__ void ldsm_x4(uint32_t* r, uint32_t addr) {
    asm volatile("ldmatrix.sync.aligned.m8n8.x4.shared.b16 {%0,%1,%2,%3}, [%4];"
        : "=r"(r[0]), "=r"(r[1]), "=r"(r[2]), "=r"(r[3]) : "r"(addr));
}
__device__ __forceinline__ void ldsm_x2(uint32_t* r, uint32_t addr) {
    asm volatile("ldmatrix.sync.aligned.m8n8.x2.shared.b16 {%0,%1}, [%2];"
        : "=r"(r[0]), "=r"(r[1]) : "r"(addr));
}
__device__ __forceinline__ void mma_tf32(float* d, const uint32_t* a, const uint32_t* b) {
    asm volatile(
        "mma.sync.aligned.m16n8k8.row.col.f32.tf32.tf32.f32 "
        "{%0,%1,%2,%3}, {%4,%5,%6,%7}, {%8,%9}, {%0,%1,%2,%3};"
        : "+f"(d[0]), "+f"(d[1]), "+f"(d[2]), "+f"(d[3])
        : "r"(a[0]), "r"(a[1]), "r"(a[2]), "r"(a[3]), "r"(b[0]), "r"(b[1]));
}

// 256B-row swizzle (flash-proven): 16B chunk c at row r -> c ^ (r&7)
__device__ __forceinline__ uint32_t sw256(int row, int chunk) {
    return (uint32_t)row * 256u + (uint32_t)((chunk ^ (row & 7)) << 4);
}

// ============================================================================
// tf32 tensor-core GEMM (NT): C[M,N] = A[M,K] @ B[N,K]^T + bias[N]
// NEW: BKF=64 (256B rows, sw256 swizzle) -> 16 barrier regions instead of 32,
// each with 8 ks of unrolled LDSM+mma for deeper software pipelining.
// Same warp layout (2x4, 64x32 tiles) and identical K-accumulation order.
// ============================================================================
#define BKF 64
#define G_STAGE 65536            // A 32KB + B 32KB per stage
#define GEMM_DSMEM (2 * G_STAGE + 1024)   // 132096

__global__ __launch_bounds__(256, 1)
void gemm_tf32_mma(const float* __restrict__ A,
                   const float* __restrict__ B,
                   const float* __restrict__ bias,
                   float* __restrict__ C,
                   int M, int N, int K)
{
    extern __shared__ char gsm[];
    const uint32_t raw  = smem_u32(gsm);
    const uint32_t base = (raw + 1023u) & ~1023u;
    char* pb = gsm + (base - raw);

    const int tid  = threadIdx.x;
    const int wid  = tid >> 5;
    const int lane = tid & 31;
    const int m0   = blockIdx.y * 128;
    const int n0   = blockIdx.x * 128;
    const int wm   = (wid & 1) * 64;
    const int wn   = (wid >> 1) * 32;

    // loader: row = tid>>1 (0..127), half = tid&1 -> 32 floats (8 chunks)
    const int lrow  = tid >> 1;
    const int lhalf = tid & 1;
    const float* Arow = A + (size_t)(m0 + lrow) * K + lhalf * 32;
    const float* Brow = B + (size_t)(n0 + lrow) * K + lhalf * 32;
    uint32_t st_off[8];
#pragma unroll
    for (int q = 0; q < 8; q++)
        st_off[q] = sw256(lrow, lhalf * 8 + q);

    // ldmatrix addressing (flash-style, 256B rows)
    const int arow = wm + ((lane >> 3) & 1) * 8 + (lane & 7);
    const int ach  = lane >> 4;            // chunk low bit for A x4
    const int brow = wn + (lane & 7);
    const int bch  = (lane >> 3) & 1;      // chunk low bit for B x2

    float acc[4][4][4];
#pragma unroll
    for (int i = 0; i < 4; i++)
#pragma unroll
        for (int j = 0; j < 4; j++)
#pragma unroll
            for (int r = 0; r < 4; r++) acc[i][j][r] = 0.f;

    const int KCH = K / BKF;               // 16
    float4 av[8], bv[8];

    // prologue: tile 0 -> stage 0
#pragma unroll
    for (int q = 0; q < 8; q++) {
        av[q] = *(const float4*)(Arow + q * 4);
        bv[q] = *(const float4*)(Brow + q * 4);
    }
#pragma unroll
    for (int q = 0; q < 8; q++) {
        float4 t;
        t.x = f2tf32(av[q].x); t.y = f2tf32(av[q].y);
        t.z = f2tf32(av[q].z); t.w = f2tf32(av[q].w);
        *(float4*)(pb + st_off[q]) = t;
        t.x = f2tf32(bv[q].x); t.y = f2tf32(bv[q].y);
        t.z = f2tf32(bv[q].z); t.w = f2tf32(bv[q].w);
        *(float4*)(pb + 32768 + st_off[q]) = t;
    }

    for (int kt = 0; kt < KCH; kt++) {
        __syncthreads();   // stage[kt&1] visible; other stage free

        if (kt + 1 < KCH) {
            const float* a = Arow + (size_t)(kt + 1) * BKF;
            const float* b = Brow + (size_t)(kt + 1) * BKF;
#pragma unroll
            for (int q = 0; q < 8; q++) {
                av[q] = *(const float4*)(a + q * 4);
                bv[q] = *(const float4*)(b + q * 4);
            }
        }

        const uint32_t sAa = base + (uint32_t)(kt & 1) * G_STAGE;
        const uint32_t sBa = sAa + 32768u;
#pragma unroll
        for (int ks = 0; ks < 8; ks++) {
            uint32_t afr[4][4], bfr[4][2];
#pragma unroll
            for (int mt = 0; mt < 4; mt++)
                ldsm_x4(afr[mt], sAa + sw256(arow + mt * 16, ks * 2 + ach));
#pragma unroll
            for (int nt = 0; nt < 4; nt++)
                ldsm_x2(bfr[nt], sBa + sw256(brow + nt * 8, ks * 2 + bch));
#pragma unroll
            for (int mt = 0; mt < 4; mt++)
#pragma unroll
                for (int nt = 0; nt < 4; nt++)
                    mma_tf32(acc[mt][nt], afr[mt], bfr[nt]);
        }

        if (kt + 1 < KCH) {
            char* dst = pb + ((kt + 1) & 1) * G_STAGE;
#pragma unroll
            for (int q = 0; q < 8; q++) {
                float4 t;
                t.x = f2tf32(av[q].x); t.y = f2tf32(av[q].y);
                t.z = f2tf32(av[q].z); t.w = f2tf32(av[q].w);
                *(float4*)(dst + st_off[q]) = t;
                t.x = f2tf32(bv[q].x); t.y = f2tf32(bv[q].y);
                t.z = f2tf32(bv[q].z); t.w = f2tf32(bv[q].w);
                *(float4*)(dst + 32768 + st_off[q]) = t;
            }
        }
    }

    const int rbase = m0 + wm + (lane >> 2);
    const int cbase = n0 + wn + (lane & 3) * 2;
#pragma unroll
    for (int mt = 0; mt < 4; mt++) {
        const int r0 = rbase + mt * 16;
#pragma unroll
        for (int nt = 0; nt < 4; nt++) {
            const int c = cbase + nt * 8;
            const float b0 = __ldg(bias + c);
            const float b1 = __ldg(bias + c + 1);
            float2 v0, v1;
            v0.x = acc[mt][nt][0] + b0; v0.y = acc[mt][nt][1] + b1;
            v1.x = acc[mt][nt][2] + b0; v1.y = acc[mt][nt][3] + b1;
            *(float2*)&C[(size_t)r0 * N + c]       = v0;
            *(float2*)&C[(size_t)(r0 + 8) * N + c] = v1;
        }
    }
}

// ============================================================================
// Tensor-core flash attention (tf32 mma), BQ=256 — ROUND-12 EXACT (658us WIN):
// per-m-tile sequential QK+softmax (one sacc live), PV B-frags shared.
// ============================================================================
#define BQ  256
#define BKV 64

// smem layout (bytes from 1024-aligned base):
//  sQ  [256][64]f : 0       .. 65536
//  sK  [ 64][64]f : 65536   .. 81920
//  sVT [ 64][64]f : 81920   .. 98304
//  sP  [256][64]f : 98304   .. 163840
//  sM  [64]i      : 163840  .. 164096
#define FA_SMEM (164096 + 1024)

__global__ __launch_bounds__(256, 1)
void flash_attn_tc(const float* __restrict__ qkv,
                   const int*   __restrict__ mask,
                   float*       __restrict__ out)
{
    extern __shared__ char fsm[];
    const uint32_t raw  = smem_u32(fsm);
    const uint32_t base = (raw + 1023u) & ~1023u;
    char* pb = fsm + (base - raw);
    char* sQ  = pb;
    char* sK  = pb + 65536;
    char* sVT = pb + 81920;
    char* sP  = pb + 98304;
    int*  sM  = (int*)(pb + 163840);
    const uint32_t aQ  = base;
    const uint32_t aK  = base + 65536;
    const uint32_t aVT = base + 81920;
    const uint32_t aP  = base + 98304;

    const int tid  = threadIdx.x;
    const int wid  = tid >> 5;
    const int lane = tid & 31;
    const int qb   = blockIdx.x;     // 0..7
    const int h    = blockIdx.y;
    const int b    = blockIdx.z;

    const size_t rs = 3 * EMBED;
    const float* qg = qkv + (size_t)(b * SEQ) * rs + h * HDIM;
    const float* kg = qg + EMBED;
    const float* vg = qg + 2 * EMBED;
    const int*   mg = mask + b * SEQ;

    // ---- load Q tile [256][64]: one row per thread, 16 chunks
    {
        const float* src = qg + (size_t)(qb * BQ + tid) * rs;
#pragma unroll
        for (int c = 0; c < 16; c++) {
            float4 v = *(const float4*)(src + c * 4);
            v.x = f2tf32(v.x); v.y = f2tf32(v.y);
            v.z = f2tf32(v.z); v.w = f2tf32(v.w);
            *(float4*)(sQ + sw256(tid, c)) = v;
        }
    }
    __syncthreads();

    // ---- hoist Q fragments: 2 m-tiles x 8 k-steps
    const int arow0 = wid * 32 + ((lane >> 3) & 1) * 8 + (lane & 7);
    const int ach   = lane >> 4;
    uint32_t qf[2][8][4];
#pragma unroll
    for (int mt = 0; mt < 2; mt++)
#pragma unroll
        for (int ks = 0; ks < 8; ks++)
            ldsm_x4(qf[mt][ks], aQ + sw256(arow0 + mt * 16, ks * 2 + ach));

    const int bln = lane & 7;
    const int bch = (lane >> 3) & 1;

    float m_i[2][2], l_i[2][2];
#pragma unroll
    for (int mt = 0; mt < 2; mt++) {
        m_i[mt][0] = -1e30f; m_i[mt][1] = -1e30f;
        l_i[mt][0] = 0.f;    l_i[mt][1] = 0.f;
    }
    float oacc[2][8][4];
#pragma unroll
    for (int mt = 0; mt < 2; mt++)
#pragma unroll
        for (int j = 0; j < 8; j++)
#pragma unroll
            for (int r = 0; r < 4; r++) oacc[mt][j][r] = 0.f;

    for (int kt = 0; kt < SEQ / BKV; kt++) {
        __syncthreads();   // prev PV mma done reading sK/sVT/sP

        // ---- load K tile [64 keys][64 d]: row = tid>>2, 4 chunks
        {
            const int r  = tid >> 2;
            const int cb = (tid & 3) * 4;
            const float* src = kg + (size_t)(kt * BKV + r) * rs;
#pragma unroll
            for (int q = 0; q < 4; q++) {
                const int c = cb + q;
                float4 v = *(const float4*)(src + c * 4);
                v.x = f2tf32(v.x); v.y = f2tf32(v.y);
                v.z = f2tf32(v.z); v.w = f2tf32(v.w);
                *(float4*)(sK + sw256(r, c)) = v;
            }
        }
        // ---- load V tile transposed -> sVT[d][key]
        {
            const int key = tid >> 2;
            const int db  = (tid & 3) * 16;
            const float* src = vg + (size_t)(kt * BKV + key) * rs + db;
            const int kc = key >> 2;
            const int kb = (key & 3) * 4;
#pragma unroll
            for (int q = 0; q < 4; q++) {
                float4 v = *(const float4*)(src + q * 4);
                const int d0 = db + q * 4;
                *(float*)(sVT + sw256(d0 + 0, kc) + kb) = f2tf32(v.x);
                *(float*)(sVT + sw256(d0 + 1, kc) + kb) = f2tf32(v.y);
                *(float*)(sVT + sw256(d0 + 2, kc) + kb) = f2tf32(v.z);
                *(float*)(sVT + sw256(d0 + 3, kc) + kb) = f2tf32(v.w);
            }
        }
        if (tid < BKV) sM[tid] = mg[kt * BKV + tid];
        __syncthreads();

        // ---- per m-tile: S = Q K^T, softmax, P store (sequential: one sacc live)
#pragma unroll
        for (int mt = 0; mt < 2; mt++) {
            float sacc[8][4];
#pragma unroll
            for (int j = 0; j < 8; j++)
#pragma unroll
                for (int r = 0; r < 4; r++) sacc[j][r] = 0.f;
#pragma unroll
            for (int ks = 0; ks < 8; ks++) {
                uint32_t bfr[8][2];
#pragma unroll
                for (int nf = 0; nf < 8; nf++)
                    ldsm_x2(bfr[nf], aK + sw256(nf * 8 + bln, ks * 2 + bch));
#pragma unroll
                for (int nf = 0; nf < 8; nf++)
                    mma_tf32(sacc[nf], qf[mt][ks], bfr[nf]);
            }

            float rmax0 = -1e30f, rmax1 = -1e30f;
#pragma unroll
            for (int j = 0; j < 8; j++) {
                const int c = j * 8 + (lane & 3) * 2;
                const int mk0 = sM[c], mk1 = sM[c + 1];
                sacc[j][0] = mk0 ? sacc[j][0] * 0.125f : -1e30f;
                sacc[j][1] = mk1 ? sacc[j][1] * 0.125f : -1e30f;
                sacc[j][2] = mk0 ? sacc[j][2] * 0.125f : -1e30f;
                sacc[j][3] = mk1 ? sacc[j][3] * 0.125f : -1e30f;
                rmax0 = fmaxf(rmax0, fmaxf(sacc[j][0], sacc[j][1]));
                rmax1 = fmaxf(rmax1, fmaxf(sacc[j][2], sacc[j][3]));
            }
            rmax0 = fmaxf(rmax0, __shfl_xor_sync(0xffffffffu, rmax0, 1));
            rmax0 = fmaxf(rmax0, __shfl_xor_sync(0xffffffffu, rmax0, 2));
            rmax1 = fmaxf(rmax1, __shfl_xor_sync(0xffffffffu, rmax1, 1));
            rmax1 = fmaxf(rmax1, __shfl_xor_sync(0xffffffffu, rmax1, 2));

            const float mn0 = fmaxf(m_i[mt][0], rmax0);
            const float mn1 = fmaxf(m_i[mt][1], rmax1);
            const float cr0 = __expf(m_i[mt][0] - mn0);
            const float cr1 = __expf(m_i[mt][1] - mn1);
            m_i[mt][0] = mn0; m_i[mt][1] = mn1;

            float rsum0 = 0.f, rsum1 = 0.f;
#pragma unroll
            for (int j = 0; j < 8; j++) {
                sacc[j][0] = __expf(sacc[j][0] - mn0);
                sacc[j][1] = __expf(sacc[j][1] - mn0);
                sacc[j][2] = __expf(sacc[j][2] - mn1);
                sacc[j][3] = __expf(sacc[j][3] - mn1);
                rsum0 += sacc[j][0] + sacc[j][1];
                rsum1 += sacc[j][2] + sacc[j][3];
            }
            rsum0 += __shfl_xor_sync(0xffffffffu, rsum0, 1);
            rsum0 += __shfl_xor_sync(0xffffffffu, rsum0, 2);
            rsum1 += __shfl_xor_sync(0xffffffffu, rsum1, 1);
            rsum1 += __shfl_xor_sync(0xffffffffu, rsum1, 2);
            l_i[mt][0] = l_i[mt][0] * cr0 + rsum0;
            l_i[mt][1] = l_i[mt][1] * cr1 + rsum1;

#pragma unroll
            for (int j = 0; j < 8; j++) {
                oacc[mt][j][0] *= cr0; oacc[mt][j][1] *= cr0;
                oacc[mt][j][2] *= cr1; oacc[mt][j][3] *= cr1;
            }

            const int r0 = wid * 32 + mt * 16 + (lane >> 2);
#pragma unroll
            for (int j = 0; j < 8; j++) {
                const int c = j * 8 + (lane & 3) * 2;
                const int ch = c >> 2;
                const int cb = (c & 3) * 4;
                float2 v0, v1;
                v0.x = f2tf32(sacc[j][0]); v0.y = f2tf32(sacc[j][1]);
                v1.x = f2tf32(sacc[j][2]); v1.y = f2tf32(sacc[j][3]);
                *(float2*)(sP + sw256(r0,     ch) + cb) = v0;
                *(float2*)(sP + sw256(r0 + 8, ch) + cb) = v1;
            }
        }
        __syncwarp();

        // ---- O += P V^T : B-fragments loaded ONCE per ks, shared by both mt
#pragma unroll
        for (int ks = 0; ks < 8; ks++) {
            uint32_t af[2][4];
#pragma unroll
            for (int mt = 0; mt < 2; mt++)
                ldsm_x4(af[mt], aP + sw256(arow0 + mt * 16, ks * 2 + ach));
            uint32_t bfr[8][2];
#pragma unroll
            for (int nf = 0; nf < 8; nf++)
                ldsm_x2(bfr[nf], aVT + sw256(nf * 8 + bln, ks * 2 + bch));
#pragma unroll
            for (int mt = 0; mt < 2; mt++)
#pragma unroll
                for (int nf = 0; nf < 8; nf++)
                    mma_tf32(oacc[mt][nf], af[mt], bfr[nf]);
        }
    }

    // ---- epilogue: normalize, write to [b, s, h*64 + d]
#pragma unroll
    for (int mt = 0; mt < 2; mt++) {
        const float inv0 = 1.0f / l_i[mt][0];
        const float inv1 = 1.0f / l_i[mt][1];
        const int r0 = qb * BQ + wid * 32 + mt * 16 + (lane >> 2);
        const int c0 = h * HDIM + (lane & 3) * 2;
#pragma unroll
        for (int j = 0; j < 8; j++) {
            const int c = c0 + j * 8;
            float2 v0, v1;
            v0.x = oacc[mt][j][0] * inv0; v0.y = oacc[mt][j][1] * inv0;
            v1.x = oacc[mt][j][2] * inv1; v1.y = oacc[mt][j][3] * inv1;
            *(float2*)&out[(size_t)(b * SEQ + r0)     * EMBED + c] = v0;
            *(float2*)&out[(size_t)(b * SEQ + r0 + 8) * EMBED + c] = v1;
        }
    }
}

// ---------------------------------------------------------------------------
extern "C" void kernel_launch(void* const* d_in, const int* in_sizes, int n_in,
                              void* d_out, int out_size)
{
    const float* x    = (const float*)d_in[0];
    const int*   mask = (const int*)  d_in[1];
    const float* Wqkv = (const float*)d_in[2];
    const float* bqkv = (const float*)d_in[3];
    const float* Wout = (const float*)d_in[4];
    const float* bout = (const float*)d_in[5];
    float* out = (float*)d_out;

    float *qkv = nullptr, *attn = nullptr;
    cudaGetSymbolAddress((void**)&qkv,  g_qkv);
    cudaGetSymbolAddress((void**)&attn, g_attn);

    cudaFuncSetAttribute(gemm_tf32_mma,
                         cudaFuncAttributeMaxDynamicSharedMemorySize, GEMM_DSMEM);
    cudaFuncSetAttribute(flash_attn_tc,
                         cudaFuncAttributeMaxDynamicSharedMemorySize, FA_SMEM);

    // 1) qkv = x @ Wqkv^T + bqkv       [4096, 3072]
    {
        dim3 grid((3 * EMBED) / 128, MTOT / 128);
        gemm_tf32_mma<<<grid, 256, GEMM_DSMEM>>>(x, Wqkv, bqkv, qkv,
                                                 MTOT, 3 * EMBED, EMBED);
    }
    // 2) flash attention -> attn       [4096, 1024]
    {
        dim3 grid(SEQ / BQ, HEADS, BATCH);
        flash_attn_tc<<<grid, 256, FA_SMEM>>>(qkv, mask, attn);
    }
    // 3) out = attn @ Wout^T + bout    [4096, 1024]
    {
        dim3 grid(EMBED / 128, MTOT / 128);
        gemm_tf32_mma<<<grid, 256, GEMM_DSMEM>>>(attn, Wout, bout, out,
                                                 MTOT, EMBED, EMBED);
    }
}

// round 15
// speedup vs baseline: 1.2542x; 1.2542x over previous
#include <cuda_runtime.h>
#include <cstdint>

#define EMBED   1024
#define HEADS   16
#define HDIM    64
#define BATCH   2
#define SEQ     2048
#define MTOT    (BATCH*SEQ)   // 4096

// Scratch (static __device__ -- no dynamic allocation allowed)
__device__ float g_qkv [(size_t)MTOT * 3 * EMBED];   // [4096, 3072]
__device__ float g_attn[(size_t)MTOT * EMBED];       // [4096, 1024]

// ============================================================================
// helpers
// ============================================================================
__device__ __forceinline__ uint32_t smem_u32(const void* p) {
    uint32_t a;
    asm("{ .reg .u64 t; cvta.to.shared.u64 t, %1; cvt.u32.u64 %0, t; }"
        : "=r"(a) : "l"(p));
    return a;
}
__device__ __forceinline__ float f2tf32(float x) {
    uint32_t u;
    asm("cvt.rna.tf32.f32 %0, %1;" : "=r"(u) : "f"(x));
    return __uint_as_float(u);
}
__device__ __forceinline__ void ldsm_x4(uint32_t* r, uint32_t addr) {
    asm volatile("ldmatrix.sync.aligned.m8n8.x4.shared.b16 {%0,%1,%2,%3}, [%4];"
        : "=r"(r[0]), "=r"(r[1]), "=r"(r[2]), "=r"(r[3]) : "r"(addr));
}
__device__ __forceinline__ void ldsm_x2(uint32_t* r, uint32_t addr) {
    asm volatile("ldmatrix.sync.aligned.m8n8.x2.shared.b16 {%0,%1}, [%2];"
        : "=r"(r[0]), "=r"(r[1]) : "r"(addr));
}
__device__ __forceinline__ void mma_tf32(float* d, const uint32_t* a, const uint32_t* b) {
    asm volatile(
        "mma.sync.aligned.m16n8k8.row.col.f32.tf32.tf32.f32 "
        "{%0,%1,%2,%3}, {%4,%5,%6,%7}, {%8,%9}, {%0,%1,%2,%3};"
        : "+f"(d[0]), "+f"(d[1]), "+f"(d[2]), "+f"(d[3])
        : "r"(a[0]), "r"(a[1]), "r"(a[2]), "r"(a[3]), "r"(b[0]), "r"(b[1]));
}
// 256B-row swizzle: 16B chunk c at row r -> c ^ (r&7)
__device__ __forceinline__ uint32_t sw256(int row, int chunk) {
    return (uint32_t)row * 256u + (uint32_t)((chunk ^ (row & 7)) << 4);
}

// ============================================================================
// tf32 tensor-core GEMM (NT): C[M,N] = A[M,K] @ B[N,K]^T + bias[N]
// ROUND-5 EXACT (best proven GEMM, frozen).
// ============================================================================
#define BKF 32
#define G_STAGE 32768
#define GEMM_DSMEM (2 * G_STAGE + 1024)

__global__ __launch_bounds__(256, 1)
void gemm_tf32_mma(const float* __restrict__ A,
                   const float* __restrict__ B,
                   const float* __restrict__ bias,
                   float* __restrict__ C,
                   int M, int N, int K)
{
    extern __shared__ char gsm[];
    const uint32_t raw  = smem_u32(gsm);
    const uint32_t base = (raw + 1023u) & ~1023u;
    char* pb = gsm + (base - raw);

    const int tid  = threadIdx.x;
    const int wid  = tid >> 5;
    const int lane = tid & 31;
    const int m0   = blockIdx.y * 128;
    const int n0   = blockIdx.x * 128;
    const int wm   = (wid & 1) * 64;
    const int wn   = (wid >> 1) * 32;

    const int lrow  = tid >> 1;
    const int lhalf = tid & 1;
    const float* Arow = A + (size_t)(m0 + lrow) * K + lhalf * 16;
    const float* Brow = B + (size_t)(n0 + lrow) * K + lhalf * 16;
    uint32_t st_off[4];
#pragma unroll
    for (int q = 0; q < 4; q++) {
        uint32_t bo = (uint32_t)lrow * 128u + (uint32_t)lhalf * 64u + q * 16u;
        st_off[q] = bo ^ ((bo >> 3) & 0x70);
    }

    const int aseg  = lane >> 3;
    const int arow  = wm + ((aseg & 1) << 3) + (lane & 7);
    const uint32_t akb = (uint32_t)((aseg >> 1) << 4);
    const int bseg  = (lane >> 3) & 1;
    const int brow  = wn + (lane & 7);
    const uint32_t bkb = (uint32_t)(bseg << 4);
    const uint32_t swmask = (uint32_t)((lane & 7) << 4);
    const uint32_t aRowByte = (uint32_t)arow * 128u;
    const uint32_t bRowByte = (uint32_t)brow * 128u;

    float acc[4][4][4];
#pragma unroll
    for (int i = 0; i < 4; i++)
#pragma unroll
        for (int j = 0; j < 4; j++)
#pragma unroll
            for (int r = 0; r < 4; r++) acc[i][j][r] = 0.f;

    const int KCH = K / BKF;
    float4 av[4], bv[4];

#pragma unroll
    for (int q = 0; q < 4; q++) {
        av[q] = *(const float4*)(Arow + q * 4);
        bv[q] = *(const float4*)(Brow + q * 4);
    }
#pragma unroll
    for (int q = 0; q < 4; q++) {
        float4 t;
        t.x = f2tf32(av[q].x); t.y = f2tf32(av[q].y);
        t.z = f2tf32(av[q].z); t.w = f2tf32(av[q].w);
        *(float4*)(pb + st_off[q]) = t;
        t.x = f2tf32(bv[q].x); t.y = f2tf32(bv[q].y);
        t.z = f2tf32(bv[q].z); t.w = f2tf32(bv[q].w);
        *(float4*)(pb + 16384 + st_off[q]) = t;
    }

    for (int kt = 0; kt < KCH; kt++) {
        __syncthreads();

        if (kt + 1 < KCH) {
            const float* a = Arow + (size_t)(kt + 1) * BKF;
            const float* b = Brow + (size_t)(kt + 1) * BKF;
#pragma unroll
            for (int q = 0; q < 4; q++) {
                av[q] = *(const float4*)(a + q * 4);
                bv[q] = *(const float4*)(b + q * 4);
            }
        }

        const uint32_t sAa = base + (uint32_t)(kt & 1) * G_STAGE;
        const uint32_t sBa = sAa + 16384u;
#pragma unroll
        for (int ks = 0; ks < 4; ks++) {
            const uint32_t kcolA = ((uint32_t)(ks * 32) + akb) ^ swmask;
            const uint32_t kcolB = ((uint32_t)(ks * 32) + bkb) ^ swmask;
            uint32_t afr[4][4], bfr[4][2];
#pragma unroll
            for (int mt = 0; mt < 4; mt++)
                ldsm_x4(afr[mt], sAa + aRowByte + (uint32_t)(mt * 16 * 128) + kcolA);
#pragma unroll
            for (int nt = 0; nt < 4; nt++)
                ldsm_x2(bfr[nt], sBa + bRowByte + (uint32_t)(nt * 8 * 128) + kcolB);
#pragma unroll
            for (int mt = 0; mt < 4; mt++)
#pragma unroll
                for (int nt = 0; nt < 4; nt++)
                    mma_tf32(acc[mt][nt], afr[mt], bfr[nt]);
        }

        if (kt + 1 < KCH) {
            char* dst = pb + ((kt + 1) & 1) * G_STAGE;
#pragma unroll
            for (int q = 0; q < 4; q++) {
                float4 t;
                t.x = f2tf32(av[q].x); t.y = f2tf32(av[q].y);
                t.z = f2tf32(av[q].z); t.w = f2tf32(av[q].w);
                *(float4*)(dst + st_off[q]) = t;
                t.x = f2tf32(bv[q].x); t.y = f2tf32(bv[q].y);
                t.z = f2tf32(bv[q].z); t.w = f2tf32(bv[q].w);
                *(float4*)(dst + 16384 + st_off[q]) = t;
            }
        }
    }

    const int rbase = m0 + wm + (lane >> 2);
    const int cbase = n0 + wn + (lane & 3) * 2;
#pragma unroll
    for (int mt = 0; mt < 4; mt++) {
        const int r0 = rbase + mt * 16;
#pragma unroll
        for (int nt = 0; nt < 4; nt++) {
            const int c = cbase + nt * 8;
            const float b0 = __ldg(bias + c);
            const float b1 = __ldg(bias + c + 1);
            float2 v0, v1;
            v0.x = acc[mt][nt][0] + b0; v0.y = acc[mt][nt][1] + b1;
            v1.x = acc[mt][nt][2] + b0; v1.y = acc[mt][nt][3] + b1;
            *(float2*)&C[(size_t)r0 * N + c]       = v0;
            *(float2*)&C[(size_t)(r0 + 8) * N + c] = v1;
        }
    }
}

// ============================================================================
// Tensor-core flash attention (tf32 mma), BQ=256 (round-12 structure)
// + double-buffered K/V/mask stages: loads for kt+1 issue before compute of
// kt, ONE __syncthreads per k-tile (loads overlap QK/softmax/PV).
// ============================================================================
#define BQ  256
#define BKV 64

// smem layout (bytes from 1024-aligned base):
//  sQ          : 0       .. 65536
//  sK  [2] st  : 65536   .. 98304   (16 KB each)
//  sVT [2] st  : 98304   .. 131072  (16 KB each)
//  sP          : 131072  .. 196608
//  sM  [2][64] : 196608  .. 197120
#define FA_K0   65536
#define FA_V0   98304
#define FA_P    131072
#define FA_M    196608
#define FA_SMEM (197120 + 1024)

__global__ __launch_bounds__(256, 1)
void flash_attn_tc(const float* __restrict__ qkv,
                   const int*   __restrict__ mask,
                   float*       __restrict__ out)
{
    extern __shared__ char fsm[];
    const uint32_t raw  = smem_u32(fsm);
    const uint32_t base = (raw + 1023u) & ~1023u;
    char* pb = fsm + (base - raw);
    char* sQ  = pb;
    char* sP  = pb + FA_P;
    int*  sM  = (int*)(pb + FA_M);          // [2][64]
    const uint32_t aQ = base;
    const uint32_t aP = base + FA_P;

    const int tid  = threadIdx.x;
    const int wid  = tid >> 5;
    const int lane = tid & 31;
    const int qb   = blockIdx.x;     // 0..7
    const int h    = blockIdx.y;
    const int b    = blockIdx.z;

    const size_t rs = 3 * EMBED;
    const float* qg = qkv + (size_t)(b * SEQ) * rs + h * HDIM;
    const float* kg = qg + EMBED;
    const float* vg = qg + 2 * EMBED;
    const int*   mg = mask + b * SEQ;

    // per-thread load mapping (row = tid>>2, 4 chunks at (tid&3)*4)
    const int lr  = tid >> 2;
    const int lcb = (tid & 3) * 4;
    const int vkc = lr >> 2;            // VT chunk for this key
    const int vkb = (lr & 3) * 4;       // byte-in-chunk

    // ---- load Q tile [256][64] + prologue K/V tile 0 into stage 0
    {
        const float* src = qg + (size_t)(qb * BQ + tid) * rs;
#pragma unroll
        for (int c = 0; c < 16; c++) {
            float4 v = *(const float4*)(src + c * 4);
            v.x = f2tf32(v.x); v.y = f2tf32(v.y);
            v.z = f2tf32(v.z); v.w = f2tf32(v.w);
            *(float4*)(sQ + sw256(tid, c)) = v;
        }
    }
    {
        char* dK = pb + FA_K0;
        char* dV = pb + FA_V0;
        const float* srck = kg + (size_t)lr * rs;
        const float* srcv = vg + (size_t)lr * rs + lcb * 4;
#pragma unroll
        for (int q = 0; q < 4; q++) {
            const int c = lcb + q;
            float4 v = *(const float4*)(srck + c * 4);
            v.x = f2tf32(v.x); v.y = f2tf32(v.y);
            v.z = f2tf32(v.z); v.w = f2tf32(v.w);
            *(float4*)(dK + sw256(lr, c)) = v;
        }
#pragma unroll
        for (int q = 0; q < 4; q++) {
            float4 v = *(const float4*)(srcv + q * 4);
            const int d0 = lcb * 4 + q * 4;
            *(float*)(dV + sw256(d0 + 0, vkc) + vkb) = f2tf32(v.x);
            *(float*)(dV + sw256(d0 + 1, vkc) + vkb) = f2tf32(v.y);
            *(float*)(dV + sw256(d0 + 2, vkc) + vkb) = f2tf32(v.z);
            *(float*)(dV + sw256(d0 + 3, vkc) + vkb) = f2tf32(v.w);
        }
        if (tid < BKV) sM[tid] = mg[tid];
    }
    __syncthreads();   // Q + stage-0 K/V visible

    // ---- hoist Q fragments: 2 m-tiles x 8 k-steps
    const int arow0 = wid * 32 + ((lane >> 3) & 1) * 8 + (lane & 7);
    const int ach   = lane >> 4;
    uint32_t qf[2][8][4];
#pragma unroll
    for (int mt = 0; mt < 2; mt++)
#pragma unroll
        for (int ks = 0; ks < 8; ks++)
            ldsm_x4(qf[mt][ks], aQ + sw256(arow0 + mt * 16, ks * 2 + ach));

    const int bln = lane & 7;
    const int bch = (lane >> 3) & 1;

    float m_i[2][2], l_i[2][2];
#pragma unroll
    for (int mt = 0; mt < 2; mt++) {
        m_i[mt][0] = -1e30f; m_i[mt][1] = -1e30f;
        l_i[mt][0] = 0.f;    l_i[mt][1] = 0.f;
    }
    float oacc[2][8][4];
#pragma unroll
    for (int mt = 0; mt < 2; mt++)
#pragma unroll
        for (int j = 0; j < 8; j++)
#pragma unroll
            for (int r = 0; r < 4; r++) oacc[mt][j][r] = 0.f;

    const int NT = SEQ / BKV;
    for (int kt = 0; kt < NT; kt++) {
        const int s = kt & 1;
        const uint32_t aK  = base + FA_K0 + (uint32_t)s * 16384u;
        const uint32_t aVT = base + FA_V0 + (uint32_t)s * 16384u;
        const int* sMc = sM + s * 64;

        // ---- issue loads for kt+1 into stage s^1 (overlaps compute below)
        if (kt + 1 < NT) {
            char* dK = pb + FA_K0 + (s ^ 1) * 16384;
            char* dV = pb + FA_V0 + (s ^ 1) * 16384;
            const float* srck = kg + (size_t)((kt + 1) * BKV + lr) * rs;
            const float* srcv = vg + (size_t)((kt + 1) * BKV + lr) * rs + lcb * 4;
#pragma unroll
            for (int q = 0; q < 4; q++) {
                const int c = lcb + q;
                float4 v = *(const float4*)(srck + c * 4);
                v.x = f2tf32(v.x); v.y = f2tf32(v.y);
                v.z = f2tf32(v.z); v.w = f2tf32(v.w);
                *(float4*)(dK + sw256(lr, c)) = v;
            }
#pragma unroll
            for (int q = 0; q < 4; q++) {
                float4 v = *(const float4*)(srcv + q * 4);
                const int d0 = lcb * 4 + q * 4;
                *(float*)(dV + sw256(d0 + 0, vkc) + vkb) = f2tf32(v.x);
                *(float*)(dV + sw256(d0 + 1, vkc) + vkb) = f2tf32(v.y);
                *(float*)(dV + sw256(d0 + 2, vkc) + vkb) = f2tf32(v.z);
                *(float*)(dV + sw256(d0 + 3, vkc) + vkb) = f2tf32(v.w);
            }
            if (tid < BKV) sM[(s ^ 1) * 64 + tid] = mg[(kt + 1) * BKV + tid];
        }

        // ---- per m-tile: S = Q K^T, softmax, P store (stage s)
#pragma unroll
        for (int mt = 0; mt < 2; mt++) {
            float sacc[8][4];
#pragma unroll
            for (int j = 0; j < 8; j++)
#pragma unroll
                for (int r = 0; r < 4; r++) sacc[j][r] = 0.f;
#pragma unroll
            for (int ks = 0; ks < 8; ks++) {
                uint32_t bfr[8][2];
#pragma unroll
                for (int nf = 0; nf < 8; nf++)
                    ldsm_x2(bfr[nf], aK + sw256(nf * 8 + bln, ks * 2 + bch));
#pragma unroll
                for (int nf = 0; nf < 8; nf++)
                    mma_tf32(sacc[nf], qf[mt][ks], bfr[nf]);
            }

            float rmax0 = -1e30f, rmax1 = -1e30f;
#pragma unroll
            for (int j = 0; j < 8; j++) {
                const int c = j * 8 + (lane & 3) * 2;
                const int mk0 = sMc[c], mk1 = sMc[c + 1];
                sacc[j][0] = mk0 ? sacc[j][0] * 0.125f : -1e30f;
                sacc[j][1] = mk1 ? sacc[j][1] * 0.125f : -1e30f;
                sacc[j][2] = mk0 ? sacc[j][2] * 0.125f : -1e30f;
                sacc[j][3] = mk1 ? sacc[j][3] * 0.125f : -1e30f;
                rmax0 = fmaxf(rmax0, fmaxf(sacc[j][0], sacc[j][1]));
                rmax1 = fmaxf(rmax1, fmaxf(sacc[j][2], sacc[j][3]));
            }
            rmax0 = fmaxf(rmax0, __shfl_xor_sync(0xffffffffu, rmax0, 1));
            rmax0 = fmaxf(rmax0, __shfl_xor_sync(0xffffffffu, rmax0, 2));
            rmax1 = fmaxf(rmax1, __shfl_xor_sync(0xffffffffu, rmax1, 1));
            rmax1 = fmaxf(rmax1, __shfl_xor_sync(0xffffffffu, rmax1, 2));

            const float mn0 = fmaxf(m_i[mt][0], rmax0);
            const float mn1 = fmaxf(m_i[mt][1], rmax1);
            const float cr0 = __expf(m_i[mt][0] - mn0);
            const float cr1 = __expf(m_i[mt][1] - mn1);
            m_i[mt][0] = mn0; m_i[mt][1] = mn1;

            float rsum0 = 0.f, rsum1 = 0.f;
#pragma unroll
            for (int j = 0; j < 8; j++) {
                sacc[j][0] = __expf(sacc[j][0] - mn0);
                sacc[j][1] = __expf(sacc[j][1] - mn0);
                sacc[j][2] = __expf(sacc[j][2] - mn1);
                sacc[j][3] = __expf(sacc[j][3] - mn1);
                rsum0 += sacc[j][0] + sacc[j][1];
                rsum1 += sacc[j][2] + sacc[j][3];
            }
            rsum0 += __shfl_xor_sync(0xffffffffu, rsum0, 1);
            rsum0 += __shfl_xor_sync(0xffffffffu, rsum0, 2);
            rsum1 += __shfl_xor_sync(0xffffffffu, rsum1, 1);
            rsum1 += __shfl_xor_sync(0xffffffffu, rsum1, 2);
            l_i[mt][0] = l_i[mt][0] * cr0 + rsum0;
            l_i[mt][1] = l_i[mt][1] * cr1 + rsum1;

#pragma unroll
            for (int j = 0; j < 8; j++) {
                oacc[mt][j][0] *= cr0; oacc[mt][j][1] *= cr0;
                oacc[mt][j][2] *= cr1; oacc[mt][j][3] *= cr1;
            }

            const int r0 = wid * 32 + mt * 16 + (lane >> 2);
#pragma unroll
            for (int j = 0; j < 8; j++) {
                const int c = j * 8 + (lane & 3) * 2;
                const int ch = c >> 2;
                const int cb = (c & 3) * 4;
                float2 v0, v1;
                v0.x = f2tf32(sacc[j][0]); v0.y = f2tf32(sacc[j][1]);
                v1.x = f2tf32(sacc[j][2]); v1.y = f2tf32(sacc[j][3]);
                *(float2*)(sP + sw256(r0,     ch) + cb) = v0;
                *(float2*)(sP + sw256(r0 + 8, ch) + cb) = v1;
            }
        }
        __syncwarp();

        // ---- O += P V^T : B-fragments loaded ONCE per ks, shared by both mt
#pragma unroll
        for (int ks = 0; ks < 8; ks++) {
            uint32_t af[2][4];
#pragma unroll
            for (int mt = 0; mt < 2; mt++)
                ldsm_x4(af[mt], aP + sw256(arow0 + mt * 16, ks * 2 + ach));
            uint32_t bfr[8][2];
#pragma unroll
            for (int nf = 0; nf < 8; nf++)
                ldsm_x2(bfr[nf], aVT + sw256(nf * 8 + bln, ks * 2 + bch));
#pragma unroll
            for (int mt = 0; mt < 2; mt++)
#pragma unroll
                for (int nf = 0; nf < 8; nf++)
                    mma_tf32(oacc[mt][nf], af[mt], bfr[nf]);
        }

        __syncthreads();   // stage s fully read; stage s^1 writes visible
    }

    // ---- epilogue: normalize, write to [b, s, h*64 + d]
#pragma unroll
    for (int mt = 0; mt < 2; mt++) {
        const float inv0 = 1.0f / l_i[mt][0];
        const float inv1 = 1.0f / l_i[mt][1];
        const int r0 = qb * BQ + wid * 32 + mt * 16 + (lane >> 2);
        const int c0 = h * HDIM + (lane & 3) * 2;
#pragma unroll
        for (int j = 0; j < 8; j++) {
            const int c = c0 + j * 8;
            float2 v0, v1;
            v0.x = oacc[mt][j][0] * inv0; v0.y = oacc[mt][j][1] * inv0;
            v1.x = oacc[mt][j][2] * inv1; v1.y = oacc[mt][j][3] * inv1;
            *(float2*)&out[(size_t)(b * SEQ + r0)     * EMBED + c] = v0;
            *(float2*)&out[(size_t)(b * SEQ + r0 + 8) * EMBED + c] = v1;
        }
    }
}

// ---------------------------------------------------------------------------
extern "C" void kernel_launch(void* const* d_in, const int* in_sizes, int n_in,
                              void* d_out, int out_size)
{
    const float* x    = (const float*)d_in[0];
    const int*   mask = (const int*)  d_in[1];
    const float* Wqkv = (const float*)d_in[2];
    const float* bqkv = (const float*)d_in[3];
    const float* Wout = (const float*)d_in[4];
    const float* bout = (const float*)d_in[5];
    float* out = (float*)d_out;

    float *qkv = nullptr, *attn = nullptr;
    cudaGetSymbolAddress((void**)&qkv,  g_qkv);
    cudaGetSymbolAddress((void**)&attn, g_attn);

    cudaFuncSetAttribute(gemm_tf32_mma,
                         cudaFuncAttributeMaxDynamicSharedMemorySize, GEMM_DSMEM);
    cudaFuncSetAttribute(flash_attn_tc,
                         cudaFuncAttributeMaxDynamicSharedMemorySize, FA_SMEM);

    // 1) qkv = x @ Wqkv^T + bqkv       [4096, 3072]
    {
        dim3 grid((3 * EMBED) / 128, MTOT / 128);
        gemm_tf32_mma<<<grid, 256, GEMM_DSMEM>>>(x, Wqkv, bqkv, qkv,
                                                 MTOT, 3 * EMBED, EMBED);
    }
    // 2) flash attention -> attn       [4096, 1024]
    {
        dim3 grid(SEQ / BQ, HEADS, BATCH);
        flash_attn_tc<<<grid, 256, FA_SMEM>>>(qkv, mask, attn);
    }
    // 3) out = attn @ Wout^T + bout    [4096, 1024]
    {
        dim3 grid(EMBED / 128, MTOT / 128);
        gemm_tf32_mma<<<grid, 256, GEMM_DSMEM>>>(attn, Wout, bout, out,
                                                 MTOT, EMBED, EMBED);
    }
}